// round 8
// baseline (speedup 1.0000x reference)
#include <cuda_runtime.h>
#include <cuda_fp16.h>
#include <cstdint>

// Problem constants
#define B_ 64
#define T_ 1024
#define E_ 128
#define F_ 64
#define C_ 5
#define TILE_T 128
#define XROWS (TILE_T + C_ - 1)   // 132

// smem layout (dynamic): bias + A window only
#define SM_BIAS 0                        // 64 floats (256B)
#define SM_A    1024                     // 132 rows x 256B (128 fp16) = 33792
#define SM_TOTAL (SM_A + XROWS * 256)    // 34816 bytes -> 4 CTAs/SM (reg-limited)

// W pre-permuted into mma B-fragment layout:
// uint32 index = (((c*8+ks)*4 + p)*32 + lane)*4 + comp,
//   tile = 2p + (comp>>1), j = comp&1
//   value = half2( W[tile*8 + lane/4][c*128+ks*16+2*(lane%4)+8j], [..+1] )
__device__ __align__(16) uint32_t g_Wfrag[C_ * 8 * 4 * 32 * 4];   // 81920 B

static __device__ __forceinline__ uint32_t smem_u32(const void* p) {
    uint32_t a;
    asm("{ .reg .u64 t; cvta.to.shared.u64 t, %1; cvt.u32.u64 %0, t; }" : "=r"(a) : "l"(p));
    return a;
}
static __device__ __forceinline__ void ldsm4(uint32_t r[4], uint32_t addr) {
    asm volatile("ldmatrix.sync.aligned.m8n8.x4.shared.b16 {%0,%1,%2,%3}, [%4];"
                 : "=r"(r[0]), "=r"(r[1]), "=r"(r[2]), "=r"(r[3]) : "r"(addr));
}
static __device__ __forceinline__ void mma_fp16(float (&d)[4], const uint32_t a[4],
                                                uint32_t b0, uint32_t b1) {
    asm volatile(
        "mma.sync.aligned.m16n8k16.row.col.f32.f16.f16.f32 "
        "{%0,%1,%2,%3}, {%4,%5,%6,%7}, {%8,%9}, {%0,%1,%2,%3};"
        : "+f"(d[0]), "+f"(d[1]), "+f"(d[2]), "+f"(d[3])
        : "r"(a[0]), "r"(a[1]), "r"(a[2]), "r"(a[3]), "r"(b0), "r"(b1));
}

// Setup: W fp32 -> fragment-major fp16 (once per launch)
__global__ void convert_w_frag_kernel(const float* __restrict__ W) {
    int idx = blockIdx.x * 256 + threadIdx.x;        // uint32 index
    if (idx >= C_ * 8 * 4 * 32 * 4) return;
    int comp = idx & 3;
    int l    = (idx >> 2) & 31;
    int p    = (idx >> 7) & 3;
    int s    = idx >> 9;                 // c*8 + ks, 0..39
    int c    = s >> 3;
    int ks   = s & 7;
    int tile = 2 * p + (comp >> 1);
    int j    = comp & 1;
    int f    = tile * 8 + (l >> 2);
    int kk   = c * E_ + ks * 16 + 2 * (l & 3) + 8 * j;
    const float* wr = W + (size_t)f * (C_ * E_) + kk;
    __half2 h = __floats2half2_rn(wr[0], wr[1]);
    g_Wfrag[idx] = *(uint32_t*)&h;
}

__global__ __launch_bounds__(128, 4)
void qa_cnn_hmma_kernel(const float* __restrict__ x,
                        const float* __restrict__ bias,
                        float* __restrict__ out)
{
    extern __shared__ char smc[];
    const uint32_t sbase = smem_u32(smc);
    const int tid = threadIdx.x;
    const int wid = tid >> 5;            // warp_m: 0..3 (32 tokens each)
    const int lid = tid & 31;
    const int b   = blockIdx.y;
    const int t0  = blockIdx.x * TILE_T;

    float* bias_s = (float*)(smc + SM_BIAS);
    if (tid < F_) bias_s[tid] = bias[tid];

    // ---- stage A window once: x[b, t0-2 .. t0+129], 132 x 128 fp32 -> fp16 ----
    const float* xb = x + (size_t)b * T_ * E_;
#pragma unroll
    for (int it = 0; it < (XROWS * 32) / 128; ++it) {   // 33 iters
        int idx = tid + it * 128;
        int row = idx >> 5;
        int e4  = (idx & 31) << 2;
        int t   = t0 - 2 + row;
        float4 v = make_float4(0.f, 0.f, 0.f, 0.f);
        if (t >= 0 && t < T_) v = *(const float4*)(xb + (size_t)t * E_ + e4);
        __half2 p0 = __floats2half2_rn(v.x, v.y);
        __half2 p1 = __floats2half2_rn(v.z, v.w);
        uint32_t off = (uint32_t)row * 256u +
                       (((uint32_t)(e4 << 1)) ^ (((uint32_t)row & 7u) << 4));
        *(uint2*)(smc + SM_A + off) = make_uint2(*(uint32_t*)&p0, *(uint32_t*)&p1);
    }
    __syncthreads();

    const int arow   = lid & 15;
    const int achalf = lid >> 4;

    // B fragment pointer: uint4 index = (s*4 + p)*32 + lid
    const uint4* gw = (const uint4*)g_Wfrag + lid;

    float acc[2][8][4];
#pragma unroll
    for (int m = 0; m < 2; ++m)
#pragma unroll
        for (int q = 0; q < 8; ++q)
#pragma unroll
            for (int r = 0; r < 4; ++r) acc[m][q][r] = 0.f;

    for (int c = 0; c < C_; ++c) {
        const int row_w = c + wid * 32 + arow;
        const uint32_t a_base = sbase + SM_A + (uint32_t)row_w * 256u;
        const uint32_t a_swz  = ((uint32_t)row_w & 7u) << 4;

#pragma unroll
        for (int ks = 0; ks < 8; ++ks) {
            const int s = c * 8 + ks;
            // B fragments: 4 x LDG.128, full n64, L1-resident
            uint4 w0 = gw[(size_t)(s * 4)     * 32];
            uint4 w1 = gw[(size_t)(s * 4 + 1) * 32];
            uint4 w2 = gw[(size_t)(s * 4 + 2) * 32];
            uint4 w3 = gw[(size_t)(s * 4 + 3) * 32];

            // A fragments: m32 x k16 (two m16 tiles)
            uint32_t aoff = ((uint32_t)(ks * 32 + achalf * 16)) ^ a_swz;
            uint32_t a0[4], a1[4];
            ldsm4(a0, a_base + aoff);
            ldsm4(a1, a_base + 4096u + aoff);    // +16 rows

#pragma unroll
            for (int m = 0; m < 2; ++m) {
                const uint32_t* am = m ? a1 : a0;
                mma_fp16(acc[m][0], am, w0.x, w0.y);
                mma_fp16(acc[m][1], am, w0.z, w0.w);
                mma_fp16(acc[m][2], am, w1.x, w1.y);
                mma_fp16(acc[m][3], am, w1.z, w1.w);
                mma_fp16(acc[m][4], am, w2.x, w2.y);
                mma_fp16(acc[m][5], am, w2.z, w2.w);
                mma_fp16(acc[m][6], am, w3.x, w3.y);
                mma_fp16(acc[m][7], am, w3.z, w3.w);
            }
        }
    }

    // ---- epilogue: acc -> out[b][f][t] + bias ----
    const int tb = t0 + wid * 32 + (lid >> 2);
    const int fc = (lid & 3) * 2;
    float* ob = out + (size_t)b * F_ * T_;
#pragma unroll
    for (int m = 0; m < 2; ++m) {
#pragma unroll
        for (int q = 0; q < 8; ++q) {
            int f = q * 8 + fc;
            int t = tb + m * 16;
            float bf0 = bias_s[f], bf1 = bias_s[f + 1];
            ob[(size_t)f * T_ + t]           = acc[m][q][0] + bf0;
            ob[(size_t)(f + 1) * T_ + t]     = acc[m][q][1] + bf1;
            ob[(size_t)f * T_ + t + 8]       = acc[m][q][2] + bf0;
            ob[(size_t)(f + 1) * T_ + t + 8] = acc[m][q][3] + bf1;
        }
    }
}

extern "C" void kernel_launch(void* const* d_in, const int* in_sizes, int n_in,
                              void* d_out, int out_size)
{
    const float* x    = (const float*)d_in[0];  // [B, T, E]
    const float* W    = (const float*)d_in[1];  // [F, C*E]
    const float* bias = (const float*)d_in[2];  // [F]
    float* out = (float*)d_out;                 // [B, F, T]

    convert_w_frag_kernel<<<(C_ * 8 * 4 * 32 * 4 + 255) / 256, 256>>>(W);

    cudaFuncSetAttribute(qa_cnn_hmma_kernel,
                         cudaFuncAttributeMaxDynamicSharedMemorySize, SM_TOTAL);
    dim3 grid(T_ / TILE_T, B_);   // 8 x 64 = 512 CTAs -> single wave at 4 CTAs/SM
    qa_cnn_hmma_kernel<<<grid, 128, SM_TOTAL>>>(x, bias, out);
}

// round 10
// speedup vs baseline: 1.0795x; 1.0795x over previous
#include <cuda_runtime.h>
#include <cuda_fp16.h>
#include <cstdint>

// Problem constants
#define B_ 64
#define T_ 1024
#define E_ 128
#define F_ 64
#define C_ 5
#define TILE_T 64
#define XROWS (TILE_T + C_ - 1)   // 68

// smem layout (dynamic): bias + A window only
#define SM_BIAS 0                        // 64 floats (256B)
#define SM_A    1024                     // 68 rows x 256B (128 fp16) = 17408
#define SM_TOTAL (SM_A + XROWS * 256)    // 18432 bytes

// W pre-permuted into mma B-fragment layout:
// uint32 index = (((c*8+ks)*4 + p)*32 + lane)*4 + comp,
//   tile = 2p + (comp>>1), j = comp&1
//   value = half2( W[tile*8 + lane/4][c*128+ks*16+2*(lane%4)+8j], [..+1] )
__device__ __align__(16) uint32_t g_Wfrag[C_ * 8 * 4 * 32 * 4];   // 81920 B

static __device__ __forceinline__ uint32_t smem_u32(const void* p) {
    uint32_t a;
    asm("{ .reg .u64 t; cvta.to.shared.u64 t, %1; cvt.u32.u64 %0, t; }" : "=r"(a) : "l"(p));
    return a;
}
static __device__ __forceinline__ void ldsm4(uint32_t r[4], uint32_t addr) {
    asm volatile("ldmatrix.sync.aligned.m8n8.x4.shared.b16 {%0,%1,%2,%3}, [%4];"
                 : "=r"(r[0]), "=r"(r[1]), "=r"(r[2]), "=r"(r[3]) : "r"(addr));
}
static __device__ __forceinline__ void mma_fp16(float (&d)[4], const uint32_t a[4],
                                                uint32_t b0, uint32_t b1) {
    asm volatile(
        "mma.sync.aligned.m16n8k16.row.col.f32.f16.f16.f32 "
        "{%0,%1,%2,%3}, {%4,%5,%6,%7}, {%8,%9}, {%0,%1,%2,%3};"
        : "+f"(d[0]), "+f"(d[1]), "+f"(d[2]), "+f"(d[3])
        : "r"(a[0]), "r"(a[1]), "r"(a[2]), "r"(a[3]), "r"(b0), "r"(b1));
}

// Setup: W fp32 -> fragment-major fp16 (once per launch)
__global__ void convert_w_frag_kernel(const float* __restrict__ W) {
    int idx = blockIdx.x * 256 + threadIdx.x;        // uint32 index
    if (idx >= C_ * 8 * 4 * 32 * 4) return;
    int comp = idx & 3;
    int l    = (idx >> 2) & 31;
    int p    = (idx >> 7) & 3;
    int s    = idx >> 9;                 // c*8 + ks, 0..39
    int c    = s >> 3;
    int ks   = s & 7;
    int tile = 2 * p + (comp >> 1);
    int j    = comp & 1;
    int f    = tile * 8 + (l >> 2);
    int kk   = c * E_ + ks * 16 + 2 * (l & 3) + 8 * j;
    const float* wr = W + (size_t)f * (C_ * E_) + kk;
    __half2 h = __floats2half2_rn(wr[0], wr[1]);
    g_Wfrag[idx] = *(uint32_t*)&h;
}

__global__ __launch_bounds__(128, 6)
void qa_cnn_hmma_kernel(const float* __restrict__ x,
                        const float* __restrict__ bias,
                        float* __restrict__ out)
{
    extern __shared__ char smc[];
    const uint32_t sbase = smem_u32(smc);
    const int tid = threadIdx.x;
    const int wid = tid >> 5;
    const int lid = tid & 31;
    const int b   = blockIdx.y;
    const int t0  = blockIdx.x * TILE_T;

    float* bias_s = (float*)(smc + SM_BIAS);
    if (tid < F_) bias_s[tid] = bias[tid];

    // ---- stage A window once: x[b, t0-2 .. t0+65], 68 x 128 fp32 -> fp16 ----
    const float* xb = x + (size_t)b * T_ * E_;
#pragma unroll
    for (int it = 0; it < (XROWS * 32) / 128; ++it) {   // 17 iters
        int idx = tid + it * 128;
        int row = idx >> 5;
        int e4  = (idx & 31) << 2;
        int t   = t0 - 2 + row;
        float4 v = make_float4(0.f, 0.f, 0.f, 0.f);
        if (t >= 0 && t < T_) v = *(const float4*)(xb + (size_t)t * E_ + e4);
        __half2 p0 = __floats2half2_rn(v.x, v.y);
        __half2 p1 = __floats2half2_rn(v.z, v.w);
        uint32_t off = (uint32_t)row * 256u +
                       (((uint32_t)(e4 << 1)) ^ (((uint32_t)row & 7u) << 4));
        *(uint2*)(smc + SM_A + off) = make_uint2(*(uint32_t*)&p0, *(uint32_t*)&p1);
    }
    __syncthreads();

    // Warp tiling: warp_m 0..1 (32 tokens), warp_f 0..1 (32 filters)
    const int warp_m = wid & 1;
    const int warp_f = wid >> 1;

    const int arow   = lid & 15;
    const int achalf = lid >> 4;

    // B fragment pointer: uint4 index = (s*4 + warp_f*2 + pl)*32 + lid
    const uint4* gw = (const uint4*)g_Wfrag + (size_t)(warp_f * 2) * 32 + lid;

    // A base address per tap (row shifts by 1 per tap)
    const int row_w0 = warp_m * 32 + arow;
    const uint32_t a_base0 = sbase + SM_A + (uint32_t)row_w0 * 256u;

    float acc[2][4][4];
#pragma unroll
    for (int m = 0; m < 2; ++m)
#pragma unroll
        for (int q = 0; q < 4; ++q)
#pragma unroll
            for (int r = 0; r < 4; ++r) acc[m][q][r] = 0.f;

    // Double-buffered fragments
    uint32_t abuf[2][2][4];   // [parity][mtile][reg]
    uint4    wbuf[2][2];      // [parity][pl]

    // Loads for step s (c = s>>3, ks = s&7); constant-folds under full unroll.
#define LOAD_STEP(s, par)                                                        \
    {                                                                            \
        int c_  = (s) >> 3;                                                      \
        int ks_ = (s) & 7;                                                       \
        uint32_t swz_  = (((uint32_t)(row_w0 + c_)) & 7u) << 4;                  \
        uint32_t aoff_ = ((uint32_t)(ks_ * 32) + (uint32_t)(achalf * 16)) ^ swz_;\
        uint32_t ab_   = a_base0 + (uint32_t)(c_ * 256);                         \
        ldsm4(abuf[par][0], ab_ + aoff_);                                        \
        ldsm4(abuf[par][1], ab_ + 4096u + aoff_);                                \
        wbuf[par][0] = gw[(size_t)((s) * 4)     * 32];                           \
        wbuf[par][1] = gw[(size_t)((s) * 4 + 1) * 32];                           \
    }

    LOAD_STEP(0, 0)

#pragma unroll
    for (int s = 0; s < 40; ++s) {
        const int cur = s & 1;
        const int nxt = cur ^ 1;
        // prefetch next step's fragments before consuming current ones
        if (s + 1 < 40) { LOAD_STEP(s + 1, nxt) }

#pragma unroll
        for (int m = 0; m < 2; ++m) {
            const uint32_t* am = abuf[cur][m];
            mma_fp16(acc[m][0], am, wbuf[cur][0].x, wbuf[cur][0].y);
            mma_fp16(acc[m][1], am, wbuf[cur][0].z, wbuf[cur][0].w);
            mma_fp16(acc[m][2], am, wbuf[cur][1].x, wbuf[cur][1].y);
            mma_fp16(acc[m][3], am, wbuf[cur][1].z, wbuf[cur][1].w);
        }
    }
#undef LOAD_STEP

    // ---- epilogue: acc -> out[b][f][t] + bias ----
    const int tb  = t0 + warp_m * 32 + (lid >> 2);
    const int fc  = (lid & 3) * 2;
    float* ob = out + (size_t)b * F_ * T_;
#pragma unroll
    for (int m = 0; m < 2; ++m) {
#pragma unroll
        for (int q = 0; q < 4; ++q) {
            int f = warp_f * 32 + q * 8 + fc;
            int t = tb + m * 16;
            float bf0 = bias_s[f], bf1 = bias_s[f + 1];
            ob[(size_t)f * T_ + t]           = acc[m][q][0] + bf0;
            ob[(size_t)(f + 1) * T_ + t]     = acc[m][q][1] + bf1;
            ob[(size_t)f * T_ + t + 8]       = acc[m][q][2] + bf0;
            ob[(size_t)(f + 1) * T_ + t + 8] = acc[m][q][3] + bf1;
        }
    }
}

extern "C" void kernel_launch(void* const* d_in, const int* in_sizes, int n_in,
                              void* d_out, int out_size)
{
    const float* x    = (const float*)d_in[0];  // [B, T, E]
    const float* W    = (const float*)d_in[1];  // [F, C*E]
    const float* bias = (const float*)d_in[2];  // [F]
    float* out = (float*)d_out;                 // [B, F, T]

    convert_w_frag_kernel<<<(C_ * 8 * 4 * 32 * 4 + 255) / 256, 256>>>(W);

    cudaFuncSetAttribute(qa_cnn_hmma_kernel,
                         cudaFuncAttributeMaxDynamicSharedMemorySize, SM_TOTAL);
    dim3 grid(T_ / TILE_T, B_);   // 16 x 64 = 1024 CTAs
    qa_cnn_hmma_kernel<<<grid, 128, SM_TOTAL>>>(x, bias, out);
}

// round 11
// speedup vs baseline: 1.0857x; 1.0057x over previous
#include <cuda_runtime.h>
#include <cuda_fp16.h>
#include <cstdint>

// Problem constants
#define B_ 64
#define T_ 1024
#define E_ 128
#define F_ 64
#define C_ 5
#define TILE_T 64
#define XROWS (TILE_T + C_ - 1)   // 68

// smem layout (dynamic): bias + A window (A region reused as fp32 transpose buffer)
#define SM_BIAS 0                        // 64 floats (256B)
#define SM_A    1024                     // 68 rows x 256B = 17408 (>= 64*66*4 = 16896)
#define SM_TOTAL (SM_A + XROWS * 256)    // 18432 bytes -> 6 CTAs/SM (reg-limited)

// W pre-permuted into mma B-fragment layout:
// uint32 index = (((c*8+ks)*4 + p)*32 + lane)*4 + comp,
//   tile = 2p + (comp>>1), j = comp&1
//   value = half2( W[tile*8 + lane/4][c*128+ks*16+2*(lane%4)+8j], [..+1] )
__device__ __align__(16) uint32_t g_Wfrag[C_ * 8 * 4 * 32 * 4];   // 81920 B

static __device__ __forceinline__ uint32_t smem_u32(const void* p) {
    uint32_t a;
    asm("{ .reg .u64 t; cvta.to.shared.u64 t, %1; cvt.u32.u64 %0, t; }" : "=r"(a) : "l"(p));
    return a;
}
static __device__ __forceinline__ void ldsm4(uint32_t r[4], uint32_t addr) {
    asm volatile("ldmatrix.sync.aligned.m8n8.x4.shared.b16 {%0,%1,%2,%3}, [%4];"
                 : "=r"(r[0]), "=r"(r[1]), "=r"(r[2]), "=r"(r[3]) : "r"(addr));
}
static __device__ __forceinline__ void mma_fp16(float (&d)[4], const uint32_t a[4],
                                                uint32_t b0, uint32_t b1) {
    asm volatile(
        "mma.sync.aligned.m16n8k16.row.col.f32.f16.f16.f32 "
        "{%0,%1,%2,%3}, {%4,%5,%6,%7}, {%8,%9}, {%0,%1,%2,%3};"
        : "+f"(d[0]), "+f"(d[1]), "+f"(d[2]), "+f"(d[3])
        : "r"(a[0]), "r"(a[1]), "r"(a[2]), "r"(a[3]), "r"(b0), "r"(b1));
}

// Setup: W fp32 -> fragment-major fp16 (once per launch)
__global__ void convert_w_frag_kernel(const float* __restrict__ W) {
    int idx = blockIdx.x * 256 + threadIdx.x;        // uint32 index
    if (idx >= C_ * 8 * 4 * 32 * 4) return;
    int comp = idx & 3;
    int l    = (idx >> 2) & 31;
    int p    = (idx >> 7) & 3;
    int s    = idx >> 9;                 // c*8 + ks, 0..39
    int c    = s >> 3;
    int ks   = s & 7;
    int tile = 2 * p + (comp >> 1);
    int j    = comp & 1;
    int f    = tile * 8 + (l >> 2);
    int kk   = c * E_ + ks * 16 + 2 * (l & 3) + 8 * j;
    const float* wr = W + (size_t)f * (C_ * E_) + kk;
    __half2 h = __floats2half2_rn(wr[0], wr[1]);
    g_Wfrag[idx] = *(uint32_t*)&h;
}

__global__ __launch_bounds__(128, 6)
void qa_cnn_hmma_kernel(const float* __restrict__ x,
                        const float* __restrict__ bias,
                        float* __restrict__ out)
{
    extern __shared__ char smc[];
    const uint32_t sbase = smem_u32(smc);
    const int tid = threadIdx.x;
    const int wid = tid >> 5;
    const int lid = tid & 31;
    const int b   = blockIdx.y;
    const int t0  = blockIdx.x * TILE_T;

    float* bias_s = (float*)(smc + SM_BIAS);
    if (tid < F_) bias_s[tid] = bias[tid];

    // ---- stage A window once: x[b, t0-2 .. t0+65], 68 x 128 fp32 -> fp16 ----
    const float* xb = x + (size_t)b * T_ * E_;
#pragma unroll
    for (int it = 0; it < (XROWS * 32) / 128; ++it) {   // 17 iters
        int idx = tid + it * 128;
        int row = idx >> 5;
        int e4  = (idx & 31) << 2;
        int t   = t0 - 2 + row;
        float4 v = make_float4(0.f, 0.f, 0.f, 0.f);
        if (t >= 0 && t < T_) v = *(const float4*)(xb + (size_t)t * E_ + e4);
        __half2 p0 = __floats2half2_rn(v.x, v.y);
        __half2 p1 = __floats2half2_rn(v.z, v.w);
        uint32_t off = (uint32_t)row * 256u +
                       (((uint32_t)(e4 << 1)) ^ (((uint32_t)row & 7u) << 4));
        *(uint2*)(smc + SM_A + off) = make_uint2(*(uint32_t*)&p0, *(uint32_t*)&p1);
    }
    __syncthreads();

    // Warp tiling: warp_m 0..1 (32 tokens), warp_f 0..1 (32 filters)
    const int warp_m = wid & 1;
    const int warp_f = wid >> 1;

    const int arow   = lid & 15;
    const int achalf = lid >> 4;

    // B fragment pointer: uint4 index = (s*4 + warp_f*2 + pl)*32 + lid
    const uint4* gw = (const uint4*)g_Wfrag + (size_t)(warp_f * 2) * 32 + lid;

    const int row_w0 = warp_m * 32 + arow;
    const uint32_t a_base0 = sbase + SM_A + (uint32_t)row_w0 * 256u;

    float acc[2][4][4];
#pragma unroll
    for (int m = 0; m < 2; ++m)
#pragma unroll
        for (int q = 0; q < 4; ++q)
#pragma unroll
            for (int r = 0; r < 4; ++r) acc[m][q][r] = 0.f;

    // Depth-2 pipeline, 2 buffers (slot = s & 1), no extra registers:
    // consume slot at step s, then immediately reload it for step s+2.
    uint32_t abuf[2][2][4];   // [slot][mtile][reg]
    uint4    wbuf[2][2];      // [slot][pl]

#define LOAD_STEP(s, slot)                                                       \
    {                                                                            \
        int c_  = (s) >> 3;                                                      \
        int ks_ = (s) & 7;                                                       \
        uint32_t swz_  = (((uint32_t)(row_w0 + c_)) & 7u) << 4;                  \
        uint32_t aoff_ = ((uint32_t)(ks_ * 32) + (uint32_t)(achalf * 16)) ^ swz_;\
        uint32_t ab_   = a_base0 + (uint32_t)(c_ * 256);                         \
        ldsm4(abuf[slot][0], ab_ + aoff_);                                       \
        ldsm4(abuf[slot][1], ab_ + 4096u + aoff_);                               \
        wbuf[slot][0] = gw[(size_t)((s) * 4)     * 32];                          \
        wbuf[slot][1] = gw[(size_t)((s) * 4 + 1) * 32];                          \
    }

    LOAD_STEP(0, 0)
    LOAD_STEP(1, 1)

#pragma unroll
    for (int s = 0; s < 40; ++s) {
        const int cur = s & 1;
#pragma unroll
        for (int m = 0; m < 2; ++m) {
            const uint32_t* am = abuf[cur][m];
            mma_fp16(acc[m][0], am, wbuf[cur][0].x, wbuf[cur][0].y);
            mma_fp16(acc[m][1], am, wbuf[cur][0].z, wbuf[cur][0].w);
            mma_fp16(acc[m][2], am, wbuf[cur][1].x, wbuf[cur][1].y);
            mma_fp16(acc[m][3], am, wbuf[cur][1].z, wbuf[cur][1].w);
        }
        if (s + 2 < 40) { LOAD_STEP(s + 2, cur) }
    }
#undef LOAD_STEP

    // ---- epilogue: transpose through smem, then coalesced streaming stores ----
    __syncthreads();   // all LDSM from SM_A done; safe to overwrite
    float* so = (float*)(smc + SM_A);    // so[f*66 + t], 64x66 floats

    const int t_base = warp_m * 32 + (lid >> 2);
    const int f_base = warp_f * 32 + (lid & 3) * 2;
#pragma unroll
    for (int m = 0; m < 2; ++m) {
#pragma unroll
        for (int q = 0; q < 4; ++q) {
            int f = f_base + q * 8;
            int t = t_base + m * 16;
            so[f * 66 + t]             = acc[m][q][0];
            so[(f + 1) * 66 + t]       = acc[m][q][1];
            so[f * 66 + t + 8]         = acc[m][q][2];
            so[(f + 1) * 66 + t + 8]   = acc[m][q][3];
        }
    }
    __syncthreads();

    float* ob = out + (size_t)b * F_ * T_ + t0;
#pragma unroll
    for (int k = 0; k < 16; ++k) {
        int f = wid * 16 + k;
        float bb = bias_s[f];
        float v0 = so[f * 66 + lid];
        float v1 = so[f * 66 + 32 + lid];
        __stcs(ob + (size_t)f * T_ + lid, v0 + bb);
        __stcs(ob + (size_t)f * T_ + 32 + lid, v1 + bb);
    }
}

extern "C" void kernel_launch(void* const* d_in, const int* in_sizes, int n_in,
                              void* d_out, int out_size)
{
    const float* x    = (const float*)d_in[0];  // [B, T, E]
    const float* W    = (const float*)d_in[1];  // [F, C*E]
    const float* bias = (const float*)d_in[2];  // [F]
    float* out = (float*)d_out;                 // [B, F, T]

    convert_w_frag_kernel<<<(C_ * 8 * 4 * 32 * 4 + 255) / 256, 256>>>(W);

    cudaFuncSetAttribute(qa_cnn_hmma_kernel,
                         cudaFuncAttributeMaxDynamicSharedMemorySize, SM_TOTAL);
    dim3 grid(T_ / TILE_T, B_);   // 16 x 64 = 1024 CTAs
    qa_cnn_hmma_kernel<<<grid, 128, SM_TOTAL>>>(x, bias, out);
}